// round 7
// baseline (speedup 1.0000x reference)
#include <cuda_runtime.h>

#define N_NODES 40000
#define N_EDGES 640000
#define D 128
#define BM 64
#define CAP 64          // per-node bucket capacity (deg ~ Poisson(16))
#define XS_STRIDE 132

// Scratch (device globals — no allocation allowed)
__device__ float g_wt[D * D];           // W^T: g_wt[i*D + o] = W[o*D + i]
__device__ int   g_cur[N_NODES];        // bucket cursors == in-degree
__device__ int   g_bkt[N_NODES * CAP];  // 10 MB: src indices bucketed by dst

__device__ __forceinline__ bool idx_is64(const void* p) {
    const int* q = (const int*)p;
    return ((q[1] | q[3] | q[5] | q[7]) == 0);
}
__device__ __forceinline__ int load_idx(const void* p, int e, bool is64) {
    return is64 ? (int)reinterpret_cast<const long long*>(p)[e]
                : reinterpret_cast<const int*>(p)[e];
}

// ---------------------------------------------------------------------------
// 1) Bucket scatter, 4 edges/thread (4 independent LDG->ATOMG->STG chains).
//    Blocks >= 625 transpose W on the side.
// ---------------------------------------------------------------------------
__global__ void __launch_bounds__(256) scatter_kernel(
    const void* __restrict__ src, const void* __restrict__ dst,
    const float* __restrict__ W)
{
    int b = blockIdx.x, t = threadIdx.x;
    if (b >= N_EDGES / 1024) {              // 64 W-transpose blocks
        int idx = (b - N_EDGES / 1024) * 256 + t;
        g_wt[(idx & 127) * D + (idx >> 7)] = W[idx];
        return;
    }
    bool is64 = idx_is64(dst);
    int e0 = (b * 256 + t) * 4;

    int d[4], s[4];
    #pragma unroll
    for (int q = 0; q < 4; ++q) {
        d[q] = load_idx(dst, e0 + q, is64);
        s[q] = load_idx(src, e0 + q, is64);
    }
    int pos[4];
    #pragma unroll
    for (int q = 0; q < 4; ++q)
        pos[q] = atomicAdd(g_cur + d[q], 1);
    #pragma unroll
    for (int q = 0; q < 4; ++q)
        if (pos[q] < CAP) g_bkt[d[q] * CAP + pos[q]] = s[q];
}

// ---------------------------------------------------------------------------
// 2) Fused aggregate + GEMM. Block = 64 nodes.
//    Phase 1: 8 warps x 8 nodes: register gather-sum, normalized row ->
//             straight into the smem x tile (no g_x round trip).
//    Phase 2: full-K-resident GEMM: out = x @ W^T + b, fma.rn.f32x2.
// ---------------------------------------------------------------------------
__global__ void __launch_bounds__(256) fused_kernel(
    const float* __restrict__ feat,
    const float* __restrict__ bias,
    float* __restrict__ out)
{
    extern __shared__ float smem[];
    float* ws = smem;                       // [128][128] == g_wt verbatim
    float* xs = smem + D * D;               // [64][132]

    const int t    = threadIdx.x;
    const int r0   = blockIdx.x * BM;       // 625 * 64 = 40000 exact
    const int warp = t >> 5;
    const int lane = t & 31;

    // Stage W^T: linear conflict-free copy (16 float4 / thread).
    {
        const float4* src4 = (const float4*)g_wt;
        float4* dst4 = (float4*)ws;
        #pragma unroll
        for (int i = 0; i < 16; ++i)
            dst4[t + i * 256] = src4[t + i * 256];
    }

    // Phase 1: aggregate 8 nodes per warp, write rows into xs.
    for (int i = 0; i < 8; ++i) {
        int r = warp * 8 + i;
        int n = r0 + r;
        int deg = min(g_cur[n], CAP);
        const int* bkt = g_bkt + n * CAP;

        float4 sum = make_float4(0.f, 0.f, 0.f, 0.f);
        for (int j = 0; j < deg; j += 32) {
            int m = min(32, deg - j);
            int myidx = (lane < m) ? bkt[j + lane] : 0;
            #pragma unroll 4
            for (int q = 0; q < m; ++q) {
                int s = __shfl_sync(0xffffffffu, myidx, q);
                float4 a = reinterpret_cast<const float4*>(feat + (size_t)s * D)[lane];
                sum.x += a.x; sum.y += a.y; sum.z += a.z; sum.w += a.w;
            }
        }
        float inv = 1.0f / (float)max(deg, 1);
        float4 f = reinterpret_cast<const float4*>(feat + (size_t)n * D)[lane];
        *(float4*)&xs[r * XS_STRIDE + lane * 4] =
            make_float4(sum.x * f.x * inv, sum.y * f.y * inv,
                        sum.z * f.z * inv, sum.w * f.w * inv);
    }
    __syncthreads();

    // Phase 2: GEMM. 4 rows x 8 cols per thread.
    const int tr = t >> 4;                  // 0..15 -> rows tr*4..+3
    const int tc = t & 15;                  // cols tc*4..+3, 64+tc*4..+3

    unsigned long long acc[4][4];
    #pragma unroll
    for (int j = 0; j < 4; ++j)
        #pragma unroll
        for (int p = 0; p < 4; ++p) acc[j][p] = 0ULL;

    #pragma unroll 8
    for (int kk = 0; kk < D; ++kk) {
        float av[4];
        av[0] = xs[(tr * 4 + 0) * XS_STRIDE + kk];
        av[1] = xs[(tr * 4 + 1) * XS_STRIDE + kk];
        av[2] = xs[(tr * 4 + 2) * XS_STRIDE + kk];
        av[3] = xs[(tr * 4 + 3) * XS_STRIDE + kk];

        ulonglong2 wA = *(const ulonglong2*)&ws[kk * D + tc * 4];
        ulonglong2 wB = *(const ulonglong2*)&ws[kk * D + 64 + tc * 4];

        #pragma unroll
        for (int j = 0; j < 4; ++j) {
            unsigned long long xp;
            asm("mov.b64 %0, {%1, %1};" : "=l"(xp) : "f"(av[j]));
            asm("fma.rn.f32x2 %0, %1, %2, %0;" : "+l"(acc[j][0]) : "l"(xp), "l"(wA.x));
            asm("fma.rn.f32x2 %0, %1, %2, %0;" : "+l"(acc[j][1]) : "l"(xp), "l"(wA.y));
            asm("fma.rn.f32x2 %0, %1, %2, %0;" : "+l"(acc[j][2]) : "l"(xp), "l"(wB.x));
            asm("fma.rn.f32x2 %0, %1, %2, %0;" : "+l"(acc[j][3]) : "l"(xp), "l"(wB.y));
        }
    }

    float4 bA = *(const float4*)(bias + tc * 4);
    float4 bB = *(const float4*)(bias + 64 + tc * 4);
    #pragma unroll
    for (int j = 0; j < 4; ++j) {
        int r = r0 + tr * 4 + j;
        float v0, v1, v2, v3;
        asm("mov.b64 {%0, %1}, %2;" : "=f"(v0), "=f"(v1) : "l"(acc[j][0]));
        asm("mov.b64 {%0, %1}, %2;" : "=f"(v2), "=f"(v3) : "l"(acc[j][1]));
        float4 oA = make_float4(v0 + bA.x, v1 + bA.y, v2 + bA.z, v3 + bA.w);
        asm("mov.b64 {%0, %1}, %2;" : "=f"(v0), "=f"(v1) : "l"(acc[j][2]));
        asm("mov.b64 {%0, %1}, %2;" : "=f"(v2), "=f"(v3) : "l"(acc[j][3]));
        float4 oB = make_float4(v0 + bB.x, v1 + bB.y, v2 + bB.z, v3 + bB.w);
        *(float4*)(out + (size_t)r * D + tc * 4)      = oA;
        *(float4*)(out + (size_t)r * D + 64 + tc * 4) = oB;
    }
}

// ---------------------------------------------------------------------------
extern "C" void kernel_launch(void* const* d_in, const int* in_sizes, int n_in,
                              void* d_out, int out_size) {
    const float* feat = (const float*)d_in[0];
    const void*  src  = d_in[1];
    const void*  dst  = d_in[2];
    const float* W    = (const float*)d_in[3];
    const float* b    = (const float*)d_in[4];
    float*       out  = (float*)d_out;

    void* cur_ptr = nullptr;
    cudaGetSymbolAddress(&cur_ptr, g_cur);

    const int smem_bytes = (D * D + BM * XS_STRIDE) * sizeof(float);  // 99328
    cudaFuncSetAttribute(fused_kernel,
                         cudaFuncAttributeMaxDynamicSharedMemorySize, smem_bytes);

    cudaMemsetAsync(cur_ptr, 0, sizeof(int) * N_NODES);

    scatter_kernel<<<N_EDGES / 1024 + 64, 256>>>(src, dst, W);  // + W^T blocks
    fused_kernel<<<N_NODES / BM, 256, smem_bytes>>>(feat, b, out);
}

// round 8
// speedup vs baseline: 1.2498x; 1.2498x over previous
#include <cuda_runtime.h>

#define N_NODES 40000
#define N_EDGES 640000
#define D 128
#define BM 64
#define CAP 64          // per-node bucket capacity (deg ~ Poisson(16))
#define XS_STRIDE 132

// Scratch (device globals — no allocation allowed)
__device__ float g_x[N_NODES * D];      // 20 MB: normalized x rows
__device__ float g_wt[D * D];           // W^T: g_wt[i*D + o] = W[o*D + i]
__device__ int   g_cur[N_NODES];        // bucket cursors == in-degree
__device__ int   g_bkt[N_NODES * CAP];  // 10 MB: src indices bucketed by dst

__device__ __forceinline__ bool idx_is64(const void* p) {
    const int* q = (const int*)p;
    return ((q[1] | q[3] | q[5] | q[7]) == 0);
}
__device__ __forceinline__ int load_idx(const void* p, int e, bool is64) {
    return is64 ? (int)reinterpret_cast<const long long*>(p)[e]
                : reinterpret_cast<const int*>(p)[e];
}

// ---------------------------------------------------------------------------
// 1) Bucket scatter, 4 edges/thread (4 independent LDG->ATOMG->STG chains,
//    MLP=4). Blocks >= 625 transpose W on the side.
// ---------------------------------------------------------------------------
__global__ void __launch_bounds__(256) scatter_kernel(
    const void* __restrict__ src, const void* __restrict__ dst,
    const float* __restrict__ W)
{
    int b = blockIdx.x, t = threadIdx.x;
    if (b >= N_EDGES / 1024) {              // 64 W-transpose blocks
        int idx = (b - N_EDGES / 1024) * 256 + t;
        g_wt[(idx & 127) * D + (idx >> 7)] = W[idx];
        return;
    }
    bool is64 = idx_is64(dst);
    int e0 = (b * 256 + t) * 4;

    int d[4], s[4];
    #pragma unroll
    for (int q = 0; q < 4; ++q) {
        d[q] = load_idx(dst, e0 + q, is64);
        s[q] = load_idx(src, e0 + q, is64);
    }
    int pos[4];
    #pragma unroll
    for (int q = 0; q < 4; ++q)
        pos[q] = atomicAdd(g_cur + d[q], 1);
    #pragma unroll
    for (int q = 0; q < 4; ++q)
        if (pos[q] < CAP) g_bkt[d[q] * CAP + pos[q]] = s[q];
}

// ---------------------------------------------------------------------------
// 2) Aggregate: one warp per node (high occupancy — latency-bound phase).
//    Dual accumulators break the FADD chain; __ldg read-only path.
// ---------------------------------------------------------------------------
__global__ void __launch_bounds__(256) agg_kernel(const float* __restrict__ feat)
{
    int n    = (blockIdx.x * 256 + threadIdx.x) >> 5;   // 5000 blocks * 8 warps
    int lane = threadIdx.x & 31;
    if (n >= N_NODES) return;

    int deg = min(g_cur[n], CAP);
    const int* bkt = g_bkt + n * CAP;

    float4 sum0 = make_float4(0.f, 0.f, 0.f, 0.f);
    float4 sum1 = make_float4(0.f, 0.f, 0.f, 0.f);
    for (int j = 0; j < deg; j += 32) {
        int m = min(32, deg - j);
        int myidx = (lane < m) ? bkt[j + lane] : 0;
        #pragma unroll 8
        for (int q = 0; q < m; ++q) {
            int s = __shfl_sync(0xffffffffu, myidx, q);
            float4 a = __ldg(reinterpret_cast<const float4*>(feat + (size_t)s * D) + lane);
            if (q & 1) {
                sum1.x += a.x; sum1.y += a.y; sum1.z += a.z; sum1.w += a.w;
            } else {
                sum0.x += a.x; sum0.y += a.y; sum0.z += a.z; sum0.w += a.w;
            }
        }
    }

    float inv = 1.0f / (float)max(deg, 1);
    float4 f = __ldg(reinterpret_cast<const float4*>(feat + (size_t)n * D) + lane);
    float4 x = make_float4((sum0.x + sum1.x) * f.x * inv,
                           (sum0.y + sum1.y) * f.y * inv,
                           (sum0.z + sum1.z) * f.z * inv,
                           (sum0.w + sum1.w) * f.w * inv);
    reinterpret_cast<float4*>(g_x + (size_t)n * D)[lane] = x;
}

// ---------------------------------------------------------------------------
// 3) GEMM (R6-proven): out = g_x @ W^T + b. Full K resident in smem:
//    W^T 64KB verbatim + x tile 64x132. One sync, 128 K-steps, fma.rn.f32x2.
// ---------------------------------------------------------------------------
__global__ void __launch_bounds__(256) gemm_kernel(
    const float* __restrict__ bias, float* __restrict__ out)
{
    extern __shared__ float smem[];
    float* ws = smem;                       // [128][128]
    float* xs = smem + D * D;               // [64][132]

    const int t  = threadIdx.x;
    const int r0 = blockIdx.x * BM;         // 625 * 64 = 40000 exact
    const int tr = t >> 4;
    const int tc = t & 15;

    {
        const float4* src4 = (const float4*)g_wt;
        float4* dst4 = (float4*)ws;
        #pragma unroll
        for (int i = 0; i < 16; ++i)
            dst4[t + i * 256] = src4[t + i * 256];
    }
    {
        const int xr = t >> 2;
        const int xq = t & 3;
        const float4* src4 = (const float4*)(g_x + (size_t)(r0 + xr) * D + xq * 32);
        float* dstp = xs + xr * XS_STRIDE + xq * 32;
        #pragma unroll
        for (int i = 0; i < 8; ++i)
            *(float4*)(dstp + i * 4) = src4[i];
    }
    __syncthreads();

    unsigned long long acc[4][4];
    #pragma unroll
    for (int j = 0; j < 4; ++j)
        #pragma unroll
        for (int p = 0; p < 4; ++p) acc[j][p] = 0ULL;

    #pragma unroll 8
    for (int kk = 0; kk < D; ++kk) {
        float av[4];
        av[0] = xs[(tr * 4 + 0) * XS_STRIDE + kk];
        av[1] = xs[(tr * 4 + 1) * XS_STRIDE + kk];
        av[2] = xs[(tr * 4 + 2) * XS_STRIDE + kk];
        av[3] = xs[(tr * 4 + 3) * XS_STRIDE + kk];

        ulonglong2 wA = *(const ulonglong2*)&ws[kk * D + tc * 4];
        ulonglong2 wB = *(const ulonglong2*)&ws[kk * D + 64 + tc * 4];

        #pragma unroll
        for (int j = 0; j < 4; ++j) {
            unsigned long long xp;
            asm("mov.b64 %0, {%1, %1};" : "=l"(xp) : "f"(av[j]));
            asm("fma.rn.f32x2 %0, %1, %2, %0;" : "+l"(acc[j][0]) : "l"(xp), "l"(wA.x));
            asm("fma.rn.f32x2 %0, %1, %2, %0;" : "+l"(acc[j][1]) : "l"(xp), "l"(wA.y));
            asm("fma.rn.f32x2 %0, %1, %2, %0;" : "+l"(acc[j][2]) : "l"(xp), "l"(wB.x));
            asm("fma.rn.f32x2 %0, %1, %2, %0;" : "+l"(acc[j][3]) : "l"(xp), "l"(wB.y));
        }
    }

    float4 bA = *(const float4*)(bias + tc * 4);
    float4 bB = *(const float4*)(bias + 64 + tc * 4);
    #pragma unroll
    for (int j = 0; j < 4; ++j) {
        int r = r0 + tr * 4 + j;
        float v0, v1, v2, v3;
        asm("mov.b64 {%0, %1}, %2;" : "=f"(v0), "=f"(v1) : "l"(acc[j][0]));
        asm("mov.b64 {%0, %1}, %2;" : "=f"(v2), "=f"(v3) : "l"(acc[j][1]));
        float4 oA = make_float4(v0 + bA.x, v1 + bA.y, v2 + bA.z, v3 + bA.w);
        asm("mov.b64 {%0, %1}, %2;" : "=f"(v0), "=f"(v1) : "l"(acc[j][2]));
        asm("mov.b64 {%0, %1}, %2;" : "=f"(v2), "=f"(v3) : "l"(acc[j][3]));
        float4 oB = make_float4(v0 + bB.x, v1 + bB.y, v2 + bB.z, v3 + bB.w);
        *(float4*)(out + (size_t)r * D + tc * 4)      = oA;
        *(float4*)(out + (size_t)r * D + 64 + tc * 4) = oB;
    }
}

// ---------------------------------------------------------------------------
extern "C" void kernel_launch(void* const* d_in, const int* in_sizes, int n_in,
                              void* d_out, int out_size) {
    const float* feat = (const float*)d_in[0];
    const void*  src  = d_in[1];
    const void*  dst  = d_in[2];
    const float* W    = (const float*)d_in[3];
    const float* b    = (const float*)d_in[4];
    float*       out  = (float*)d_out;

    void* cur_ptr = nullptr;
    cudaGetSymbolAddress(&cur_ptr, g_cur);

    const int smem_bytes = (D * D + BM * XS_STRIDE) * sizeof(float);  // 99328
    cudaFuncSetAttribute(gemm_kernel,
                         cudaFuncAttributeMaxDynamicSharedMemorySize, smem_bytes);

    cudaMemsetAsync(cur_ptr, 0, sizeof(int) * N_NODES);

    scatter_kernel<<<N_EDGES / 1024 + 64, 256>>>(src, dst, W);  // + W^T blocks
    agg_kernel<<<(N_NODES * 32 + 255) / 256, 256>>>(feat);
    gemm_kernel<<<N_NODES / BM, 256, smem_bytes>>>(b, out);
}